// round 5
// baseline (speedup 1.0000x reference)
#include <cuda_runtime.h>
#include <cstdint>
#include <math.h>

#define DIM   8192
#define BATCH 8
#define TOPK  60
#define NSPLIT 4          // t-dimension split of the sparse gather (4 x 15 = 60)

typedef unsigned long long ull;
typedef unsigned int uint;

// ---------------- device scratch (no allocations allowed) ----------------
__device__ float g_act[BATCH * DIM];                   // step-1 sigmoid output
__device__ float g_part[NSPLIT * BATCH * DIM];         // step-2 partial dots (pre-sigmoid)
__device__ ull   g_sdr_paired[(BATCH / 2) * DIM];      // sdr packed as (b,b+1) f32 pairs
__device__ float g_vals[BATCH * 64];                   // top-k values, sorted by index
__device__ int   g_idxs[BATCH * 64];                   // top-k indices, ascending

// ---------------- helpers ----------------
__device__ __forceinline__ float sigmoidf(float x) {
    return 1.0f / (1.0f + expf(-x));   // precise expf: selection must match reference
}
__device__ __forceinline__ ull pack2(float x, float y) {
    ull r; asm("mov.b64 %0, {%1,%2};" : "=l"(r) : "f"(x), "f"(y)); return r;
}
__device__ __forceinline__ void unpack2(ull v, float &x, float &y) {
    asm("mov.b64 {%0,%1}, %2;" : "=f"(x), "=f"(y) : "l"(v));
}
__device__ __forceinline__ void fma2(ull &d, ull a, ull b) {
    asm("fma.rn.f32x2 %0, %1, %2, %0;" : "+l"(d) : "l"(a), "l"(b));
}

// ---------------- kernel 0: pack sdr into batch-pairs ----------------
__global__ void pair_sdr_kernel(const float* __restrict__ sdr) {
    int k = blockIdx.x * blockDim.x + threadIdx.x;
    if (k < DIM) {
#pragma unroll
        for (int p = 0; p < BATCH / 2; p++) {
            g_sdr_paired[p * DIM + k] =
                pack2(sdr[(2 * p) * DIM + k], sdr[(2 * p + 1) * DIM + k]);
        }
    }
}

// ---------------- kernel 1: dense GEMV-8 + sigmoid ----------------
// Warp owns 4 consecutive rows j; lanes stride over k in float4 units;
// 16 float4 lines in flight per warp body.
__global__ __launch_bounds__(256, 2) void gemv_dense_kernel(const float* __restrict__ syn) {
    int warp = blockIdx.x * 8 + (threadIdx.x >> 5);   // 2048 warps
    int lane = threadIdx.x & 31;
    int j0 = warp * 4;

    const float4* r0 = (const float4*)(syn + (size_t)(j0 + 0) * DIM);
    const float4* r1 = (const float4*)(syn + (size_t)(j0 + 1) * DIM);
    const float4* r2 = (const float4*)(syn + (size_t)(j0 + 2) * DIM);
    const float4* r3 = (const float4*)(syn + (size_t)(j0 + 3) * DIM);

    ull acc[4][4];
#pragma unroll
    for (int i = 0; i < 4; i++)
#pragma unroll
        for (int p = 0; p < 4; p++) acc[i][p] = 0ull;

    for (int t = 0; t < DIM / 4; t += 128) {          // 16 bodies
        float4 a0[4], a1[4], a2[4], a3[4];
#pragma unroll
        for (int u = 0; u < 4; u++) {
            int k4 = t + u * 32 + lane;
            a0[u] = r0[k4]; a1[u] = r1[k4]; a2[u] = r2[k4]; a3[u] = r3[k4];
        }
#pragma unroll
        for (int u = 0; u < 4; u++) {
            int k = (t + u * 32 + lane) * 4;
            ulonglong2 sA[4], sB[4];
#pragma unroll
            for (int p = 0; p < 4; p++) {
                const ulonglong2* sp = (const ulonglong2*)&g_sdr_paired[p * DIM + k];
                sA[p] = sp[0];
                sB[p] = sp[1];
            }
#pragma unroll
            for (int i = 0; i < 4; i++) {
                float4 a = (i == 0 ? a0[u] : i == 1 ? a1[u] : i == 2 ? a2[u] : a3[u]);
                ull px = pack2(a.x, a.x), py = pack2(a.y, a.y);
                ull pz = pack2(a.z, a.z), pw = pack2(a.w, a.w);
#pragma unroll
                for (int p = 0; p < 4; p++) {
                    fma2(acc[i][p], px, sA[p].x);
                    fma2(acc[i][p], py, sA[p].y);
                    fma2(acc[i][p], pz, sB[p].x);
                    fma2(acc[i][p], pw, sB[p].y);
                }
            }
        }
    }

#pragma unroll
    for (int i = 0; i < 4; i++) {
#pragma unroll
        for (int p = 0; p < 4; p++) {
            float x, y;
            unpack2(acc[i][p], x, y);
#pragma unroll
            for (int o = 16; o > 0; o >>= 1) {
                x += __shfl_down_sync(0xFFFFFFFFu, x, o);
                y += __shfl_down_sync(0xFFFFFFFFu, y, o);
            }
            if (lane == 0) {
                g_act[(size_t)(2 * p)     * DIM + (j0 + i)] = sigmoidf(x);
                g_act[(size_t)(2 * p + 1) * DIM + (j0 + i)] = sigmoidf(y);
            }
        }
    }
}

// ---------------- kernel 2/4: per-row top-k (512 threads, coalesced) ----------------
// phase 0: read g_act -> compact (val, idx) list, SORTED by index ascending.
// phase 1: read 4 partial-dot arrays, add + sigmoid -> final dense output row.
// Exact jax.lax.top_k tie semantics (lowest index wins at the cutoff).
__global__ __launch_bounds__(512) void topk_kernel(float* __restrict__ full_out, int phase) {
    int b   = blockIdx.x;
    int tid = threadIdx.x;

    uint ub[16];
    if (phase == 0) {
        const float4* row4 = (const float4*)(g_act + (size_t)b * DIM);
#pragma unroll
        for (int i = 0; i < 4; i++) {
            float4 v = row4[i * 512 + tid];
            ub[i * 4 + 0] = __float_as_uint(v.x);
            ub[i * 4 + 1] = __float_as_uint(v.y);
            ub[i * 4 + 2] = __float_as_uint(v.z);
            ub[i * 4 + 3] = __float_as_uint(v.w);
        }
    } else {
        const float4* p0 = (const float4*)(g_part + (size_t)(0 * BATCH + b) * DIM);
        const float4* p1 = (const float4*)(g_part + (size_t)(1 * BATCH + b) * DIM);
        const float4* p2 = (const float4*)(g_part + (size_t)(2 * BATCH + b) * DIM);
        const float4* p3 = (const float4*)(g_part + (size_t)(3 * BATCH + b) * DIM);
#pragma unroll
        for (int i = 0; i < 4; i++) {
            int idx = i * 512 + tid;
            float4 a = p0[idx], c = p1[idx], d = p2[idx], e = p3[idx];
            ub[i * 4 + 0] = __float_as_uint(sigmoidf(a.x + c.x + d.x + e.x));
            ub[i * 4 + 1] = __float_as_uint(sigmoidf(a.y + c.y + d.y + e.y));
            ub[i * 4 + 2] = __float_as_uint(sigmoidf(a.z + c.z + d.z + e.z));
            ub[i * 4 + 3] = __float_as_uint(sigmoidf(a.w + c.w + d.w + e.w));
        }
    }

    __shared__ int   s_cnt[36];      // [0..31] search iters, [33] cnt_gt
    __shared__ int   s_tie[64];
    __shared__ float s_outv[64];
    __shared__ int   s_outi[64];
    __shared__ int   s_ntie, s_slot;
    if (tid < 36) s_cnt[tid] = 0;
    if (tid == 0) { s_ntie = 0; s_slot = 0; }

    if (phase == 1) {                // zero output row, overlapped with search
        float4* o4 = (float4*)(full_out + (size_t)b * DIM);
        float4 z = make_float4(0.f, 0.f, 0.f, 0.f);
#pragma unroll
        for (int i = 0; i < 4; i++) o4[i * 512 + tid] = z;
    }
    __syncthreads();

    // binary search over float bits (sigmoid output in (0,1) -> bits monotone)
    uint lo = 0u, hi = 0x3F800001u;
    int it = 0;
    while (hi - lo > 1u) {
        uint mid = lo + ((hi - lo) >> 1);
        int c = 0;
#pragma unroll
        for (int i = 0; i < 16; i++) c += (ub[i] >= mid);
#pragma unroll
        for (int o = 16; o > 0; o >>= 1) c += __shfl_xor_sync(0xFFFFFFFFu, c, o);
        if ((tid & 31) == 0) atomicAdd(&s_cnt[it], c);
        __syncthreads();
        int tot = s_cnt[it];
        it++;
        if (tot >= TOPK) lo = mid; else hi = mid;
    }
    uint T = lo;   // bits of the k-th largest value

    {
        int c = 0;
#pragma unroll
        for (int i = 0; i < 16; i++) c += (ub[i] > T);
#pragma unroll
        for (int o = 16; o > 0; o >>= 1) c += __shfl_xor_sync(0xFFFFFFFFu, c, o);
        if ((tid & 31) == 0) atomicAdd(&s_cnt[33], c);
    }
#pragma unroll
    for (int i = 0; i < 16; i++) {
        if (ub[i] == T) {
            int pos = (i >> 2) * 2048 + tid * 4 + (i & 3);
            int t = atomicAdd(&s_ntie, 1);
            if (t < 64) s_tie[t] = pos;
        }
    }
    __syncthreads();
    int cnt_gt = s_cnt[33];
    int needed = TOPK - cnt_gt;        // ties to take, lowest index first
    int ntie = min(s_ntie, 64);

    if (tid == 0) {                    // tiny insertion sort of tie positions
        for (int x = 1; x < ntie; x++) {
            int v = s_tie[x], y = x - 1;
            while (y >= 0 && s_tie[y] > v) { s_tie[y + 1] = s_tie[y]; y--; }
            s_tie[y + 1] = v;
        }
    }
    __syncthreads();
    int nsel = min(needed, 64);

    float* orow = full_out + (size_t)b * DIM;
#pragma unroll
    for (int i = 0; i < 16; i++) {
        uint u = ub[i];
        int pos = (i >> 2) * 2048 + tid * 4 + (i & 3);
        bool take = false;
        if (u > T) {
            take = true;
        } else if (u == T) {
            for (int q = 0; q < nsel; q++) take |= (s_tie[q] == pos);
        }
        if (take) {
            if (phase == 0) {
                int slot = atomicAdd(&s_slot, 1);
                s_outv[slot] = __uint_as_float(u);
                s_outi[slot] = pos;
            } else {
                orow[pos] = __uint_as_float(u);
            }
        }
    }

    if (phase == 0) {
        // parallel rank-sort the 60 selected entries by index ascending
        __syncthreads();
        if (tid < TOPK) {
            int my_i = s_outi[tid];
            float my_v = s_outv[tid];
            int rank = 0;
#pragma unroll 10
            for (int q = 0; q < TOPK; q++) rank += (s_outi[q] < my_i);
            g_vals[b * 64 + rank] = my_v;
            g_idxs[b * 64 + rank] = my_i;
        }
    }
}

// ---------------- kernel 3: sparse partial GEMV ----------------
// part[h][b][j] = sum_{t in quarter h} val[b][t] * syn[j][idx[b][t]]
// Block = 512 threads: 16 j x 8 b x 4 quarters. Grid 512 -> 8192 warps
// (~55 warps/SM) to hide the ~600-cyc scattered DRAM latency.
// Indices sorted ascending (DRAM row locality); 15 independent LDGs/thread.
__global__ __launch_bounds__(512) void gemv_sparse_kernel(const float* __restrict__ syn) {
    int tid = threadIdx.x;
    int jj = tid & 15;            // 0..15
    int b  = (tid >> 4) & 7;      // 0..7
    int h  = tid >> 7;            // 0..3 quarter
    int j  = blockIdx.x * 16 + jj;

    __shared__ float sv[BATCH * 64];
    __shared__ int   si[BATCH * 64];
    for (int t = tid; t < BATCH * 64; t += 512) {
        sv[t] = g_vals[t];
        si[t] = g_idxs[t];
    }
    __syncthreads();

    const float* __restrict__ row = syn + (size_t)j * DIM;
    int t0 = b * 64 + h * (TOPK / NSPLIT);
    float acc = 0.0f;
#pragma unroll
    for (int t = 0; t < TOPK / NSPLIT; t++) {
        acc += sv[t0 + t] * __ldg(&row[si[t0 + t]]);
    }
    g_part[(size_t)(h * BATCH + b) * DIM + j] = acc;
}

// ---------------- launch ----------------
extern "C" void kernel_launch(void* const* d_in, const int* in_sizes, int n_in,
                              void* d_out, int out_size) {
    const float* sdr = (const float*)d_in[0];   // [8, 8192]
    const float* syn = (const float*)d_in[1];   // [8192, 8192]
    float* out = (float*)d_out;                 // [8, 8192]
    (void)in_sizes; (void)n_in; (void)out_size;

    pair_sdr_kernel<<<DIM / 256, 256>>>(sdr);
    gemv_dense_kernel<<<DIM / 32, 256>>>(syn);       // 256 blocks, 4 rows/warp
    topk_kernel<<<BATCH, 512>>>(out, /*phase=*/0);   // -> sorted (val, idx)
    gemv_sparse_kernel<<<DIM / 16, 512>>>(syn);      // 512 blocks, 16j x 8b x 4h
    topk_kernel<<<BATCH, 512>>>(out, /*phase=*/1);   // combine + select + write
}

// round 6
// speedup vs baseline: 1.3298x; 1.3298x over previous
#include <cuda_runtime.h>
#include <cstdint>
#include <math.h>

#define DIM   8192
#define BATCH 8
#define TOPK  60
#define NENT  (BATCH * TOPK)   // 480 merged sparse entries

typedef unsigned long long ull;
typedef unsigned int uint;

// ---------------- device scratch (no allocations allowed) ----------------
__device__ float g_act[BATCH * DIM];               // step-1 sigmoid output
__device__ float g_z2 [BATCH * DIM];               // step-2 sigmoid output
__device__ ull   g_sdr_paired[(BATCH / 2) * DIM];  // sdr packed as (b,b+1) f32 pairs
__device__ float g_vals[BATCH * 64];               // top-k values, sorted by index (per batch)
__device__ int   g_idxs[BATCH * 64];               // top-k indices, ascending (per batch)
__device__ int   g_skey[NENT];                     // merged entries: (col<<3)|b, col-ascending
__device__ float g_sval[NENT];                     // merged entry values

// ---------------- helpers ----------------
__device__ __forceinline__ float sigmoidf(float x) {
    return 1.0f / (1.0f + expf(-x));   // precise expf: selection must match reference
}
__device__ __forceinline__ ull pack2(float x, float y) {
    ull r; asm("mov.b64 %0, {%1,%2};" : "=l"(r) : "f"(x), "f"(y)); return r;
}
__device__ __forceinline__ void unpack2(ull v, float &x, float &y) {
    asm("mov.b64 {%0,%1}, %2;" : "=f"(x), "=f"(y) : "l"(v));
}
__device__ __forceinline__ void fma2(ull &d, ull a, ull b) {
    asm("fma.rn.f32x2 %0, %1, %2, %0;" : "+l"(d) : "l"(a), "l"(b));
}

// ---------------- kernel 0: pack sdr into batch-pairs ----------------
__global__ void pair_sdr_kernel(const float* __restrict__ sdr) {
    int k = blockIdx.x * blockDim.x + threadIdx.x;
    if (k < DIM) {
#pragma unroll
        for (int p = 0; p < BATCH / 2; p++) {
            g_sdr_paired[p * DIM + k] =
                pack2(sdr[(2 * p) * DIM + k], sdr[(2 * p + 1) * DIM + k]);
        }
    }
}

// ---------------- kernel 1: dense GEMV-8 + sigmoid (unchanged from R4) ----------------
__global__ __launch_bounds__(256, 2) void gemv_dense_kernel(const float* __restrict__ syn) {
    int warp = blockIdx.x * 8 + (threadIdx.x >> 5);   // 2048 warps
    int lane = threadIdx.x & 31;
    int j0 = warp * 4;

    const float4* r0 = (const float4*)(syn + (size_t)(j0 + 0) * DIM);
    const float4* r1 = (const float4*)(syn + (size_t)(j0 + 1) * DIM);
    const float4* r2 = (const float4*)(syn + (size_t)(j0 + 2) * DIM);
    const float4* r3 = (const float4*)(syn + (size_t)(j0 + 3) * DIM);

    ull acc[4][4];
#pragma unroll
    for (int i = 0; i < 4; i++)
#pragma unroll
        for (int p = 0; p < 4; p++) acc[i][p] = 0ull;

    for (int t = 0; t < DIM / 4; t += 128) {          // 16 bodies
        float4 a0[4], a1[4], a2[4], a3[4];
#pragma unroll
        for (int u = 0; u < 4; u++) {
            int k4 = t + u * 32 + lane;
            a0[u] = r0[k4]; a1[u] = r1[k4]; a2[u] = r2[k4]; a3[u] = r3[k4];
        }
#pragma unroll
        for (int u = 0; u < 4; u++) {
            int k = (t + u * 32 + lane) * 4;
            ulonglong2 sA[4], sB[4];
#pragma unroll
            for (int p = 0; p < 4; p++) {
                const ulonglong2* sp = (const ulonglong2*)&g_sdr_paired[p * DIM + k];
                sA[p] = sp[0];
                sB[p] = sp[1];
            }
#pragma unroll
            for (int i = 0; i < 4; i++) {
                float4 a = (i == 0 ? a0[u] : i == 1 ? a1[u] : i == 2 ? a2[u] : a3[u]);
                ull px = pack2(a.x, a.x), py = pack2(a.y, a.y);
                ull pz = pack2(a.z, a.z), pw = pack2(a.w, a.w);
#pragma unroll
                for (int p = 0; p < 4; p++) {
                    fma2(acc[i][p], px, sA[p].x);
                    fma2(acc[i][p], py, sA[p].y);
                    fma2(acc[i][p], pz, sB[p].x);
                    fma2(acc[i][p], pw, sB[p].y);
                }
            }
        }
    }

#pragma unroll
    for (int i = 0; i < 4; i++) {
#pragma unroll
        for (int p = 0; p < 4; p++) {
            float x, y;
            unpack2(acc[i][p], x, y);
#pragma unroll
            for (int o = 16; o > 0; o >>= 1) {
                x += __shfl_down_sync(0xFFFFFFFFu, x, o);
                y += __shfl_down_sync(0xFFFFFFFFu, y, o);
            }
            if (lane == 0) {
                g_act[(size_t)(2 * p)     * DIM + (j0 + i)] = sigmoidf(x);
                g_act[(size_t)(2 * p + 1) * DIM + (j0 + i)] = sigmoidf(y);
            }
        }
    }
}

// ---------------- kernel 2/5: per-row top-k (R4 version) ----------------
// phase 0: read g_act -> compact (val, idx) list, sorted by index (per batch).
// phase 1: read g_z2  -> final dense output row (zeros + selected values).
__global__ __launch_bounds__(512) void topk_kernel(float* __restrict__ full_out, int phase) {
    int b   = blockIdx.x;
    int tid = threadIdx.x;
    const float* row = (phase == 0 ? g_act : g_z2) + (size_t)b * DIM;
    const float4* row4 = (const float4*)row;

    uint ub[16];
#pragma unroll
    for (int i = 0; i < 4; i++) {
        float4 v = row4[i * 512 + tid];
        ub[i * 4 + 0] = __float_as_uint(v.x);
        ub[i * 4 + 1] = __float_as_uint(v.y);
        ub[i * 4 + 2] = __float_as_uint(v.z);
        ub[i * 4 + 3] = __float_as_uint(v.w);
    }

    __shared__ int   s_cnt[36];
    __shared__ int   s_tie[64];
    __shared__ float s_outv[64];
    __shared__ int   s_outi[64];
    __shared__ int   s_ntie, s_slot;
    if (tid < 36) s_cnt[tid] = 0;
    if (tid == 0) { s_ntie = 0; s_slot = 0; }

    if (phase == 1) {                // zero output row, overlapped with search
        float4* o4 = (float4*)(full_out + (size_t)b * DIM);
        float4 z = make_float4(0.f, 0.f, 0.f, 0.f);
#pragma unroll
        for (int i = 0; i < 4; i++) o4[i * 512 + tid] = z;
    }
    __syncthreads();

    // binary search over float bits (sigmoid output in (0,1) -> bits monotone)
    uint lo = 0u, hi = 0x3F800001u;
    int it = 0;
    while (hi - lo > 1u) {
        uint mid = lo + ((hi - lo) >> 1);
        int c = 0;
#pragma unroll
        for (int i = 0; i < 16; i++) c += (ub[i] >= mid);
#pragma unroll
        for (int o = 16; o > 0; o >>= 1) c += __shfl_xor_sync(0xFFFFFFFFu, c, o);
        if ((tid & 31) == 0) atomicAdd(&s_cnt[it], c);
        __syncthreads();
        int tot = s_cnt[it];
        it++;
        if (tot >= TOPK) lo = mid; else hi = mid;
    }
    uint T = lo;

    {
        int c = 0;
#pragma unroll
        for (int i = 0; i < 16; i++) c += (ub[i] > T);
#pragma unroll
        for (int o = 16; o > 0; o >>= 1) c += __shfl_xor_sync(0xFFFFFFFFu, c, o);
        if ((tid & 31) == 0) atomicAdd(&s_cnt[33], c);
    }
#pragma unroll
    for (int i = 0; i < 16; i++) {
        if (ub[i] == T) {
            int pos = (i >> 2) * 2048 + tid * 4 + (i & 3);
            int t = atomicAdd(&s_ntie, 1);
            if (t < 64) s_tie[t] = pos;
        }
    }
    __syncthreads();
    int cnt_gt = s_cnt[33];
    int needed = TOPK - cnt_gt;
    int ntie = min(s_ntie, 64);

    if (tid == 0) {
        for (int x = 1; x < ntie; x++) {
            int v = s_tie[x], y = x - 1;
            while (y >= 0 && s_tie[y] > v) { s_tie[y + 1] = s_tie[y]; y--; }
            s_tie[y + 1] = v;
        }
    }
    __syncthreads();
    int nsel = min(needed, 64);

    float* orow = full_out + (size_t)b * DIM;
#pragma unroll
    for (int i = 0; i < 16; i++) {
        uint u = ub[i];
        int pos = (i >> 2) * 2048 + tid * 4 + (i & 3);
        bool take = false;
        if (u > T) {
            take = true;
        } else if (u == T) {
            for (int q = 0; q < nsel; q++) take |= (s_tie[q] == pos);
        }
        if (take) {
            if (phase == 0) {
                int slot = atomicAdd(&s_slot, 1);
                s_outv[slot] = __uint_as_float(u);
                s_outi[slot] = pos;
            } else {
                orow[pos] = __uint_as_float(u);
            }
        }
    }

    if (phase == 0) {
        __syncthreads();
        if (tid < TOPK) {
            int my_i = s_outi[tid];
            float my_v = s_outv[tid];
            int rank = 0;
#pragma unroll 10
            for (int q = 0; q < TOPK; q++) rank += (s_outi[q] < my_i);
            g_vals[b * 64 + rank] = my_v;
            g_idxs[b * 64 + rank] = my_i;
        }
    }
}

// ---------------- kernel 3: merge all 480 entries, sort by column ----------------
// key = (col << 3) | b  (unique) -> rank sort in one block.
__global__ __launch_bounds__(512) void sort_entries_kernel() {
    __shared__ int s_key[NENT];
    int tid = threadIdx.x;
    float my_v = 0.0f; int my_key = 0;
    if (tid < NENT) {
        int b = tid / TOPK, t = tid % TOPK;
        my_key = (g_idxs[b * 64 + t] << 3) | b;
        my_v   = g_vals[b * 64 + t];
        s_key[tid] = my_key;
    }
    __syncthreads();
    if (tid < NENT) {
        int rank = 0;
#pragma unroll 8
        for (int q = 0; q < NENT; q++) rank += (s_key[q] < my_key);
        g_skey[rank] = my_key;
        g_sval[rank] = my_v;
    }
}

// ---------------- kernel 4: sparse GEMV, warp-per-row coalesced ----------------
// z2[b][j] = sigmoid( sum over merged entries with batch b of val * syn[j][col] )
// Warp owns row j; lanes sweep the column-sorted entry list -> consecutive
// lanes read ascending columns within ONE row (contiguous DRAM windows).
// Batch separation via 8 predicated accumulators per lane.
__global__ __launch_bounds__(256) void gemv_sparse_kernel(const float* __restrict__ syn) {
    int tid  = threadIdx.x;
    int w    = tid >> 5;
    int lane = tid & 31;
    int j = blockIdx.x * 8 + w;

    __shared__ int   s_key[NENT];
    __shared__ float s_val[NENT];
    for (int t = tid; t < NENT; t += 256) {
        s_key[t] = g_skey[t];
        s_val[t] = g_sval[t];
    }
    __syncthreads();

    const float* __restrict__ row = syn + (size_t)j * DIM;
    float acc[BATCH];
#pragma unroll
    for (int bb = 0; bb < BATCH; bb++) acc[bb] = 0.0f;

#pragma unroll
    for (int i = 0; i < NENT / 32; i++) {             // 15 iterations
        int   key = s_key[i * 32 + lane];
        float v   = s_val[i * 32 + lane];
        float x   = __ldg(&row[key >> 3]);
        float p   = v * x;
        int   b   = key & 7;
#pragma unroll
        for (int bb = 0; bb < BATCH; bb++) {
            acc[bb] += (b == bb) ? p : 0.0f;
        }
    }

    // warp tree-reduction of 8 accumulators
#pragma unroll
    for (int o = 16; o > 0; o >>= 1) {
#pragma unroll
        for (int bb = 0; bb < BATCH; bb++) {
            acc[bb] += __shfl_down_sync(0xFFFFFFFFu, acc[bb], o);
        }
    }
    // lane 0 holds all 8 sums; fan out so 8 lanes do sigmoid+store in parallel
    float mine = 0.0f;
#pragma unroll
    for (int bb = 0; bb < BATCH; bb++) {
        float r = __shfl_sync(0xFFFFFFFFu, acc[bb], 0);
        if (lane == bb) mine = r;
    }
    if (lane < BATCH) {
        g_z2[(size_t)lane * DIM + j] = sigmoidf(mine);
    }
}

// ---------------- launch ----------------
extern "C" void kernel_launch(void* const* d_in, const int* in_sizes, int n_in,
                              void* d_out, int out_size) {
    const float* sdr = (const float*)d_in[0];   // [8, 8192]
    const float* syn = (const float*)d_in[1];   // [8192, 8192]
    float* out = (float*)d_out;                 // [8, 8192]
    (void)in_sizes; (void)n_in; (void)out_size;

    pair_sdr_kernel<<<DIM / 256, 256>>>(sdr);
    gemv_dense_kernel<<<DIM / 32, 256>>>(syn);       // 256 blocks, 4 rows/warp
    topk_kernel<<<BATCH, 512>>>(out, /*phase=*/0);   // -> per-batch sorted (val, idx)
    sort_entries_kernel<<<1, 512>>>();               // -> 480 entries, column-sorted
    gemv_sparse_kernel<<<DIM / 8, 256>>>(syn);       // 1024 blocks, warp-per-row
    topk_kernel<<<BATCH, 512>>>(out, /*phase=*/1);   // -> dense output rows
}